// round 14
// baseline (speedup 1.0000x reference)
#include <cuda_runtime.h>
#include <cstdint>

#define H 2048
#define B 16
#define S 256
#define V 32000
#define NBLK 128
#define NTHR 512
#define PPAD 17

__device__ float g_E[2][H * B];    // tf32-rounded exp(y_t - shift_t), dbl buffered
__device__ float g_shift[2][B];    // shift_t[b] = y_t[0,b] (block 0, row 0)
__device__ unsigned g_flag[NBLK];  // monotonic epochs: done step t => base+t+1

__device__ __forceinline__ unsigned cvt_tf32(float f) {
    unsigned r; asm("cvt.rna.tf32.f32 %0, %1;" : "=r"(r) : "f"(f)); return r;
}
__device__ __forceinline__ void mma_tf32(float* d, const unsigned* a,
                                         const unsigned* b, const float* c) {
    asm("mma.sync.aligned.m16n8k8.row.col.f32.tf32.tf32.f32 "
        "{%0,%1,%2,%3}, {%4,%5,%6,%7}, {%8,%9}, {%10,%11,%12,%13};"
        : "=f"(d[0]), "=f"(d[1]), "=f"(d[2]), "=f"(d[3])
        : "r"(a[0]), "r"(a[1]), "r"(a[2]), "r"(a[3]),
          "r"(b[0]), "r"(b[1]),
          "f"(c[0]), "f"(c[1]), "f"(c[2]), "f"(c[3]));
}
__device__ __forceinline__ void atom_rel_exch(unsigned* p, unsigned v) {
    unsigned old;
    asm volatile("atom.release.gpu.global.exch.b32 %0, [%1], %2;"
                 : "=r"(old) : "l"(p), "r"(v) : "memory");
}

// ---------------------------------------------------------------------------
// single persistent kernel: per-warp dataflow waits on producer flags,
// tf32 MMA with alpha resident in register fragments, log/exp off-chain
// ---------------------------------------------------------------------------
__global__ void __launch_bounds__(NTHR, 1) hmm_persist(
    const int* __restrict__ ids, const float* __restrict__ alpha,
    const float* __restrict__ beta, const float* __restrict__ gamma,
    float* __restrict__ out) {
    extern __shared__ float smem[];
    float* s_part0 = smem;                   // [256][PPAD] partials, buffer 0
    float* s_part1 = s_part0 + 256 * PPAD;   // [256][PPAD] partials, buffer 1
    float* s_misc = s_part1 + 256 * PPAD;    // [128] staging for final fold

    const int tid = threadIdx.x;
    const int blk = blockIdx.x;
    const int r0 = blk * 16;
    const int lane = tid & 31, w = tid >> 5;
    const int gid = lane >> 2;                 // MMA group id (0..7)
    const int tg = lane & 3;                   // thread-in-group (0..3)
    const int orow = tid >> 4, ob = tid & 15;  // epilogue mapping (tid<256)
    const bool epi = (tid < 256);
    const int kb = w * 128;                    // this warp's k slice

    __shared__ unsigned s_base;
    if (tid == 0) s_base = *(volatile unsigned*)&g_flag[blk];

    // preload alpha MMA A-fragments: rows {gid, gid+8}, cols {tg, tg+4} per ktile
    unsigned afr[16][4];
    #pragma unroll
    for (int kt = 0; kt < 16; kt++) {
        const int k0 = kb + kt * 8;
        afr[kt][0] = cvt_tf32(__ldg(&alpha[(size_t)(r0 + gid) * H + k0 + tg]));
        afr[kt][1] = cvt_tf32(__ldg(&alpha[(size_t)(r0 + gid + 8) * H + k0 + tg]));
        afr[kt][2] = cvt_tf32(__ldg(&alpha[(size_t)(r0 + gid) * H + k0 + tg + 4]));
        afr[kt][3] = cvt_tf32(__ldg(&alpha[(size_t)(r0 + gid + 8) * H + k0 + tg + 4]));
    }
    __syncthreads();
    const unsigned base = s_base;

    float m_prev = 0.f;  // shift used when E_{t-1} was published

    // ---- t = 0: y0 = masked beta gather; E_0 = tf32(exp(y0))
    {
        float y0 = 0.f;
        if (epi) {
            int id = __ldg(&ids[ob * S + (S - 1)]);
            float bv = __ldg(&beta[(size_t)(r0 + orow) * V + (id < 0 ? 0 : id)]);
            y0 = (id < 0) ? 0.f : bv;
            g_E[0][(r0 + orow) * B + ob] = __uint_as_float(cvt_tf32(__expf(y0)));
            if (blk == 0 && tid < 16) g_shift[0][tid] = y0;
        }
        __syncthreads();
        if (tid == 0) atom_rel_exch(&g_flag[blk], base + 1u);
        if (epi) out[(size_t)(r0 + orow) * B + ob] = y0;
    }

    // ---- main recurrence: per-warp waits, no top-of-loop block barrier
    for (int t = 1; t < S; t++) {
        const int par = (t - 1) & 1;
        float* s_part = (t & 1) ? s_part1 : s_part0;

        // prefetch ip (independent of any flag)
        float ipv = 0.f;
        if (epi) {
            int id = __ldg(&ids[ob * S + (S - 1 - t)]);
            float bv = __ldg(&beta[(size_t)(r0 + orow) * V + (id < 0 ? 0 : id)]);
            ipv = (id < 0) ? 0.f : bv;
        }

        // per-warp wait: producers 8w..8w+7 (lanes 0-7); lane 8 covers block 0
        // (source of g_shift) for epilogue warps
        {
            const unsigned bt = base + (unsigned)t;
            if (lane < 8) {
                volatile unsigned* f = &g_flag[w * 8 + lane];
                while (*f < bt) {}
            } else if (lane == 8) {
                volatile unsigned* f = &g_flag[0];
                while (*f < bt) {}
            }
            __syncwarp();
        }

        // scale for publishing E_t (epilogue warps only), hides under the dot:
        // E_t = sum * exp(ip + m_prev - Mb)
        float Mb = 0.f, scale = 0.f;
        if (epi) {
            Mb = __ldcg(&g_shift[par][ob]);
            scale = __expf(ipv + m_prev - Mb);
        }

        // ---- tf32 MMA dot: D[16 x 16] over this warp's 128 k
        const float* Eg = g_E[par];
        float acc0[4] = {0.f, 0.f, 0.f, 0.f};  // cols 0..7
        float acc1[4] = {0.f, 0.f, 0.f, 0.f};  // cols 8..15
        #pragma unroll
        for (int kt = 0; kt < 16; kt++) {
            const int kr = kb + kt * 8 + tg;
            unsigned b0[2], b1[2];
            b0[0] = __float_as_uint(__ldcg(&Eg[kr * B + gid]));
            b0[1] = __float_as_uint(__ldcg(&Eg[(kr + 4) * B + gid]));
            b1[0] = __float_as_uint(__ldcg(&Eg[kr * B + 8 + gid]));
            b1[1] = __float_as_uint(__ldcg(&Eg[(kr + 4) * B + 8 + gid]));
            mma_tf32(acc0, afr[kt], b0, acc0);
            mma_tf32(acc1, afr[kt], b1, acc1);
        }

        // store partials into this step's buffer
        s_part[(gid * 16 + 2 * tg) * PPAD + w] = acc0[0];
        s_part[(gid * 16 + 2 * tg + 1) * PPAD + w] = acc0[1];
        s_part[((gid + 8) * 16 + 2 * tg) * PPAD + w] = acc0[2];
        s_part[((gid + 8) * 16 + 2 * tg + 1) * PPAD + w] = acc0[3];
        s_part[(gid * 16 + 8 + 2 * tg) * PPAD + w] = acc1[0];
        s_part[(gid * 16 + 8 + 2 * tg + 1) * PPAD + w] = acc1[1];
        s_part[((gid + 8) * 16 + 8 + 2 * tg) * PPAD + w] = acc1[2];
        s_part[((gid + 8) * 16 + 8 + 2 * tg + 1) * PPAD + w] = acc1[3];
        __syncthreads();  // all 16 warps' partials visible (sole block barrier)

        // fast epilogue (warps 0-7): E_t = sum * scale; release; then log+ys
        float sum = 0.f;
        if (epi) {
            const float* pp = s_part + tid * PPAD;
            #pragma unroll
            for (int c = 0; c < 16; c++) sum += pp[c];
            g_E[t & 1][(r0 + orow) * B + ob] =
                __uint_as_float(cvt_tf32(sum * scale));
            if (blk == 0 && tid < 16)
                g_shift[t & 1][tid] = __logf(sum) + m_prev + ipv;
            asm volatile("bar.sync 1, 256;" ::: "memory");
            if (tid == 0) atom_rel_exch(&g_flag[blk], base + (unsigned)(t + 1));
            // off the critical path:
            float y = __logf(sum) + m_prev + ipv;
            out[(size_t)t * H * B + (size_t)(r0 + orow) * B + ob] = y;
            m_prev = Mb;
        }
    }

    // ---- final fold: block b (<16): final[b] = log(sum_h softmax(gamma)_h *
    //      E_{S-1}[h,b]) + g_shift[(S-2)&1][b]
    if (blk < 16) {
        if (tid < NBLK) {
            volatile unsigned* f = &g_flag[tid];
            const unsigned bs = base + (unsigned)S;
            while (*f < bs) {}
        }
        __syncthreads();

        float gv[4];
        #pragma unroll
        for (int i = 0; i < 4; i++) gv[i] = __ldg(&gamma[tid + i * NTHR]);
        float gm = fmaxf(fmaxf(gv[0], gv[1]), fmaxf(gv[2], gv[3]));
        #pragma unroll
        for (int o = 16; o > 0; o >>= 1)
            gm = fmaxf(gm, __shfl_xor_sync(0xffffffffu, gm, o));
        if (lane == 0) s_misc[64 + w] = gm;
        __syncthreads();
        float gmax = s_misc[64];
        #pragma unroll
        for (int c = 1; c < 16; c++) gmax = fmaxf(gmax, s_misc[64 + c]);

        const float* El = g_E[(S - 1) & 1];
        float qs = 0.f, sm = 0.f;
        #pragma unroll
        for (int i = 0; i < 4; i++) {
            int h = tid + i * NTHR;
            float q = __expf(gv[i] - gmax);
            qs += q;
            sm += q * __ldcg(El + (size_t)h * B + blk);
        }
        #pragma unroll
        for (int o = 16; o > 0; o >>= 1) {
            qs += __shfl_xor_sync(0xffffffffu, qs, o);
            sm += __shfl_xor_sync(0xffffffffu, sm, o);
        }
        if (lane == 0) { s_misc[w] = qs; s_misc[32 + w] = sm; }
        __syncthreads();

        if (tid == 0) {
            float gsum = 0.f, tot = 0.f;
            #pragma unroll
            for (int c = 0; c < 16; c++) { gsum += s_misc[c]; tot += s_misc[32 + c]; }
            float shift = __ldcg(&g_shift[(S - 2) & 1][blk]);
            out[(size_t)S * H * B + blk] = __logf(tot) - __logf(gsum) + shift;
        }
    }
}

// ---------------------------------------------------------------------------
extern "C" void kernel_launch(void* const* d_in, const int* in_sizes, int n_in,
                              void* d_out, int out_size) {
    const int* ids = (const int*)d_in[0];        // (B, S) int32
    const float* alpha = (const float*)d_in[1];  // (H, H)
    const float* beta = (const float*)d_in[2];   // (H, V)
    const float* gamma = (const float*)d_in[3];  // (H,)
    float* out = (float*)d_out;                  // ys (S,H,B) then final (B,)

    const int smem_main = (2 * 256 * PPAD + 128) * (int)sizeof(float);
    cudaFuncSetAttribute(hmm_persist, cudaFuncAttributeMaxDynamicSharedMemorySize,
                         smem_main);

    hmm_persist<<<NBLK, NTHR, smem_main>>>(ids, alpha, beta, gamma, out);
}

// round 15
// speedup vs baseline: 1.1836x; 1.1836x over previous
#include <cuda_runtime.h>
#include <cstdint>

#define H 2048
#define B 16
#define S 256
#define V 32000
#define NBLK 128
#define NTHR 512
#define PPAD 17
#define FSTRIDE 32  // one flag per 128B line

__device__ float g_E[2][H * B];    // tf32-rounded exp(y_t - shift_t), dbl buffered
__device__ float g_shift[2][B];    // shift_t[b] = y_t[0,b] (block 0, row 0)
__device__ unsigned g_flag[NBLK * FSTRIDE];  // padded: flag of blk at [blk*FSTRIDE]

__device__ __forceinline__ unsigned cvt_tf32(float f) {
    unsigned r; asm("cvt.rna.tf32.f32 %0, %1;" : "=r"(r) : "f"(f)); return r;
}
__device__ __forceinline__ void mma_tf32(float* d, const unsigned* a,
                                         const unsigned* b, const float* c) {
    asm("mma.sync.aligned.m16n8k8.row.col.f32.tf32.tf32.f32 "
        "{%0,%1,%2,%3}, {%4,%5,%6,%7}, {%8,%9}, {%10,%11,%12,%13};"
        : "=f"(d[0]), "=f"(d[1]), "=f"(d[2]), "=f"(d[3])
        : "r"(a[0]), "r"(a[1]), "r"(a[2]), "r"(a[3]),
          "r"(b[0]), "r"(b[1]),
          "f"(c[0]), "f"(c[1]), "f"(c[2]), "f"(c[3]));
}
__device__ __forceinline__ void st_rel(unsigned* p, unsigned v) {
    asm volatile("st.release.gpu.global.u32 [%0], %1;" :: "l"(p), "r"(v) : "memory");
}

// ---------------------------------------------------------------------------
// single persistent kernel (R13 structure): flat padded-flag barrier,
// tf32 MMA with alpha in register fragments, log/exp off the critical path
// ---------------------------------------------------------------------------
__global__ void __launch_bounds__(NTHR, 1) hmm_persist(
    const int* __restrict__ ids, const float* __restrict__ alpha,
    const float* __restrict__ beta, const float* __restrict__ gamma,
    float* __restrict__ out) {
    extern __shared__ float smem[];
    float* s_part = smem;                 // [256][PPAD] cross-warp partials
    float* s_misc = s_part + 256 * PPAD;  // [128] staging

    const int tid = threadIdx.x;
    const int blk = blockIdx.x;
    const int r0 = blk * 16;
    const int lane = tid & 31, w = tid >> 5;
    const int gid = lane >> 2;                 // MMA group id (0..7)
    const int tg = lane & 3;                   // thread-in-group (0..3)
    const int orow = tid >> 4, ob = tid & 15;  // epilogue mapping (tid<256)
    const bool epi = (tid < 256);
    const int kb = w * 128;                    // this warp's k slice

    __shared__ unsigned s_base;
    if (tid == 0) s_base = *(volatile unsigned*)&g_flag[blk * FSTRIDE];

    // preload alpha MMA A-fragments: rows {gid, gid+8}, cols {tg, tg+4} per ktile
    unsigned afr[16][4];
    #pragma unroll
    for (int kt = 0; kt < 16; kt++) {
        const int k0 = kb + kt * 8;
        afr[kt][0] = cvt_tf32(__ldg(&alpha[(size_t)(r0 + gid) * H + k0 + tg]));
        afr[kt][1] = cvt_tf32(__ldg(&alpha[(size_t)(r0 + gid + 8) * H + k0 + tg]));
        afr[kt][2] = cvt_tf32(__ldg(&alpha[(size_t)(r0 + gid) * H + k0 + tg + 4]));
        afr[kt][3] = cvt_tf32(__ldg(&alpha[(size_t)(r0 + gid + 8) * H + k0 + tg + 4]));
    }
    __syncthreads();
    const unsigned base = s_base;

    float m_prev = 0.f;  // shift used when E_{t-1} was published

    // ---- t = 0: y0 = masked beta gather; E_0 = tf32(exp(y0))
    {
        float y0 = 0.f;
        if (epi) {
            int id = __ldg(&ids[ob * S + (S - 1)]);
            float bv = __ldg(&beta[(size_t)(r0 + orow) * V + (id < 0 ? 0 : id)]);
            y0 = (id < 0) ? 0.f : bv;
            g_E[0][(r0 + orow) * B + ob] = __uint_as_float(cvt_tf32(__expf(y0)));
            if (blk == 0 && tid < 16) g_shift[0][tid] = y0;
        }
        __syncthreads();
        if (tid == 0) st_rel(&g_flag[blk * FSTRIDE], base + 1u);
        if (epi) out[(size_t)(r0 + orow) * B + ob] = y0;
    }

    // ---- main recurrence
    for (int t = 1; t < S; t++) {
        const int par = (t - 1) & 1;

        // prefetch ip (independent of any flag)
        float ipv = 0.f;
        if (epi) {
            int id = __ldg(&ids[ob * S + (S - 1 - t)]);
            float bv = __ldg(&beta[(size_t)(r0 + orow) * V + (id < 0 ? 0 : id)]);
            ipv = (id < 0) ? 0.f : bv;
        }

        // flat barrier: tid<128 each polls its own padded flag line
        if (tid < NBLK) {
            volatile unsigned* f = &g_flag[tid * FSTRIDE];
            const unsigned bt = base + (unsigned)t;
            while (*f < bt) {}
        }
        __syncthreads();

        // scale for publishing E_t, computed during the dot:
        // E_t = sum * exp(ip + m_prev - Mb)
        float Mb = 0.f, scale = 0.f;
        if (epi) {
            Mb = __ldcg(&g_shift[par][ob]);
            scale = __expf(ipv + m_prev - Mb);
        }

        // ---- tf32 MMA dot: D[16 x 16] over this warp's 128 k
        const float* Eg = g_E[par];
        float acc0[4] = {0.f, 0.f, 0.f, 0.f};  // cols 0..7
        float acc1[4] = {0.f, 0.f, 0.f, 0.f};  // cols 8..15
        #pragma unroll
        for (int kt = 0; kt < 16; kt++) {
            const int kr = kb + kt * 8 + tg;
            unsigned b0[2], b1[2];
            b0[0] = __float_as_uint(__ldcg(&Eg[kr * B + gid]));
            b0[1] = __float_as_uint(__ldcg(&Eg[(kr + 4) * B + gid]));
            b1[0] = __float_as_uint(__ldcg(&Eg[kr * B + 8 + gid]));
            b1[1] = __float_as_uint(__ldcg(&Eg[(kr + 4) * B + 8 + gid]));
            mma_tf32(acc0, afr[kt], b0, acc0);
            mma_tf32(acc1, afr[kt], b1, acc1);
        }

        // store partials: rows {gid, gid+8}, cols {2tg, 2tg+1} (+8 for acc1)
        s_part[(gid * 16 + 2 * tg) * PPAD + w] = acc0[0];
        s_part[(gid * 16 + 2 * tg + 1) * PPAD + w] = acc0[1];
        s_part[((gid + 8) * 16 + 2 * tg) * PPAD + w] = acc0[2];
        s_part[((gid + 8) * 16 + 2 * tg + 1) * PPAD + w] = acc0[3];
        s_part[(gid * 16 + 8 + 2 * tg) * PPAD + w] = acc1[0];
        s_part[(gid * 16 + 8 + 2 * tg + 1) * PPAD + w] = acc1[1];
        s_part[((gid + 8) * 16 + 8 + 2 * tg) * PPAD + w] = acc1[2];
        s_part[((gid + 8) * 16 + 8 + 2 * tg + 1) * PPAD + w] = acc1[3];
        __syncthreads();

        // fast epilogue: E_t = sum * scale (no log/exp on the chain)
        float sum = 0.f;
        if (epi) {
            const float* pp = s_part + tid * PPAD;
            #pragma unroll
            for (int c = 0; c < 16; c++) sum += pp[c];
            g_E[t & 1][(r0 + orow) * B + ob] =
                __uint_as_float(cvt_tf32(sum * scale));
            if (blk == 0 && tid < 16)
                g_shift[t & 1][tid] = __logf(sum) + m_prev + ipv;
            asm volatile("bar.sync 1, 256;" ::: "memory");
            if (tid == 0) st_rel(&g_flag[blk * FSTRIDE], base + (unsigned)(t + 1));
            // off the critical path:
            float y = __logf(sum) + m_prev + ipv;
            out[(size_t)t * H * B + (size_t)(r0 + orow) * B + ob] = y;
            m_prev = Mb;
        }
    }

    // ---- final fold: block b (<16): final[b] = log(sum_h softmax(gamma)_h *
    //      E_{S-1}[h,b]) + g_shift[(S-2)&1][b]
    if (blk < 16) {
        if (tid < NBLK) {
            volatile unsigned* f = &g_flag[tid * FSTRIDE];
            const unsigned bs = base + (unsigned)S;
            while (*f < bs) {}
        }
        __syncthreads();

        float gv[4];
        #pragma unroll
        for (int i = 0; i < 4; i++) gv[i] = __ldg(&gamma[tid + i * NTHR]);
        float gm = fmaxf(fmaxf(gv[0], gv[1]), fmaxf(gv[2], gv[3]));
        #pragma unroll
        for (int o = 16; o > 0; o >>= 1)
            gm = fmaxf(gm, __shfl_xor_sync(0xffffffffu, gm, o));
        if (lane == 0) s_misc[64 + w] = gm;
        __syncthreads();
        float gmax = s_misc[64];
        #pragma unroll
        for (int c = 1; c < 16; c++) gmax = fmaxf(gmax, s_misc[64 + c]);

        const float* El = g_E[(S - 1) & 1];
        float qs = 0.f, sm = 0.f;
        #pragma unroll
        for (int i = 0; i < 4; i++) {
            int h = tid + i * NTHR;
            float q = __expf(gv[i] - gmax);
            qs += q;
            sm += q * __ldcg(El + (size_t)h * B + blk);
        }
        #pragma unroll
        for (int o = 16; o > 0; o >>= 1) {
            qs += __shfl_xor_sync(0xffffffffu, qs, o);
            sm += __shfl_xor_sync(0xffffffffu, sm, o);
        }
        if (lane == 0) { s_misc[w] = qs; s_misc[32 + w] = sm; }
        __syncthreads();

        if (tid == 0) {
            float gsum = 0.f, tot = 0.f;
            #pragma unroll
            for (int c = 0; c < 16; c++) { gsum += s_misc[c]; tot += s_misc[32 + c]; }
            float shift = __ldcg(&g_shift[(S - 2) & 1][blk]);
            out[(size_t)S * H * B + blk] = __logf(tot) - __logf(gsum) + shift;
        }
    }
}

// ---------------------------------------------------------------------------
extern "C" void kernel_launch(void* const* d_in, const int* in_sizes, int n_in,
                              void* d_out, int out_size) {
    const int* ids = (const int*)d_in[0];        // (B, S) int32
    const float* alpha = (const float*)d_in[1];  // (H, H)
    const float* beta = (const float*)d_in[2];   // (H, V)
    const float* gamma = (const float*)d_in[3];  // (H,)
    float* out = (float*)d_out;                  // ys (S,H,B) then final (B,)

    const int smem_main = (256 * PPAD + 128) * (int)sizeof(float);
    cudaFuncSetAttribute(hmm_persist, cudaFuncAttributeMaxDynamicSharedMemorySize,
                         smem_main);

    hmm_persist<<<NBLK, NTHR, smem_main>>>(ids, alpha, beta, gamma, out);
}